// round 2
// baseline (speedup 1.0000x reference)
#include <cuda_runtime.h>
#include <stdint.h>
#include <math.h>

// Problem constants (fixed by the dataset)
#define BB 8
#define NV 500000
#define NF 1000000
#define NE (6*NF)

#define SCAN_CHUNK 1024
#define SCAN_NB ((NV + SCAN_CHUNK - 1)/SCAN_CHUNK)   // 489

// ---- device-global scratch (no cudaMalloc allowed) ----
__device__ float g_vt[(size_t)NV*24];    // transposed vertices: [N][b*3+c]  (48 MB, L2-resident)
__device__ int   g_deg[NV];              // degree histogram
__device__ int   g_off[NV+1];            // CSR offsets (exclusive scan of deg)
__device__ int   g_cur[NV];              // fill cursors
__device__ int   g_adj[NE];              // CSR adjacency (src vertex ids)
__device__ int   g_bsum[1024];           // scan block sums
__device__ float g_ct[(size_t)NV*BB];    // curvature, vertex-major [N][8]
__device__ int   g_is64;                 // faces dtype flag (1 = int64, 0 = int32)

// ---------------------------------------------------------------------------
// 0) dtype probe: if faces is int64 with values < 500000, every odd 32-bit
//    word is 0. For int32 data that is impossible over 4096 random samples.
// ---------------------------------------------------------------------------
__global__ void k_probe(const int* __restrict__ f) {
    __shared__ int any;
    if (threadIdx.x == 0) any = 0;
    __syncthreads();
    int bad = 0;
    for (int i = threadIdx.x; i < 4096; i += blockDim.x)
        if (f[2*i + 1] != 0) bad = 1;
    if (bad) atomicOr(&any, 1);
    __syncthreads();
    if (threadIdx.x == 0) g_is64 = (any == 0);
}

__device__ __forceinline__ void load_face(const void* faces, int f,
                                          int& i, int& j, int& k) {
    if (g_is64) {
        const long long* p = (const long long*)faces + (size_t)f * 3;
        i = (int)p[0]; j = (int)p[1]; k = (int)p[2];
    } else {
        const int* p = (const int*)faces + (size_t)f * 3;
        i = p[0]; j = p[1]; k = p[2];
    }
    // safety clamp: turn any surprise into a wrong-value signal, not a crash
    i = min(max(i, 0), NV - 1);
    j = min(max(j, 0), NV - 1);
    k = min(max(k, 0), NV - 1);
}

// ---------------------------------------------------------------------------
// 1) vert (B,N,3) -> vt (N, 24) ; 24 = b*3+c.  96B per vertex, contiguous.
// ---------------------------------------------------------------------------
__global__ void k_transpose(const float* __restrict__ vert) {
    __shared__ float s[64*24];
    int n0 = blockIdx.x * 64;
    int t  = threadIdx.x;                 // 192 threads
    int nrem = NV - n0; if (nrem > 64) nrem = 64;
    int cnt = nrem * 3;
    #pragma unroll
    for (int b = 0; b < 8; b++) {
        if (t < cnt) {
            int v = t / 3, c = t - v*3;
            s[v*24 + b*3 + c] = vert[(size_t)b*NV*3 + (size_t)n0*3 + t];
        }
    }
    __syncthreads();
    int tot = nrem * 24;
    for (int i = t; i < tot; i += 192)
        g_vt[(size_t)n0*24 + i] = s[i];
}

// ---------------------------------------------------------------------------
// 2) zero degree histogram (graph replays -> must re-init every launch)
// ---------------------------------------------------------------------------
__global__ void k_zero_deg() {
    int i = blockIdx.x * blockDim.x + threadIdx.x;
    if (i < NV) g_deg[i] = 0;
}

// ---------------------------------------------------------------------------
// 3) degree histogram.  Each face contributes +2 to each of its 3 vertices.
// ---------------------------------------------------------------------------
__global__ void k_hist(const void* __restrict__ faces) {
    int f = blockIdx.x * blockDim.x + threadIdx.x;
    if (f >= NF) return;
    int i, j, k;
    load_face(faces, f, i, j, k);
    atomicAdd(&g_deg[i], 2);
    atomicAdd(&g_deg[j], 2);
    atomicAdd(&g_deg[k], 2);
}

// ---------------------------------------------------------------------------
// 4) two-level exclusive scan: A=block sums, B=scan of sums, C=final offsets
// ---------------------------------------------------------------------------
__global__ void k_scanA() {
    __shared__ int s[SCAN_CHUNK];
    int i = blockIdx.x * SCAN_CHUNK + threadIdx.x;
    s[threadIdx.x] = (i < NV) ? g_deg[i] : 0;
    __syncthreads();
    for (int d = SCAN_CHUNK/2; d > 0; d >>= 1) {
        if (threadIdx.x < d) s[threadIdx.x] += s[threadIdx.x + d];
        __syncthreads();
    }
    if (threadIdx.x == 0) g_bsum[blockIdx.x] = s[0];
}

__global__ void k_scanB() {
    __shared__ int s[512];
    int t = threadIdx.x;                  // 512 threads, SCAN_NB=489 entries
    int v = (t < SCAN_NB) ? g_bsum[t] : 0;
    s[t] = v;
    __syncthreads();
    for (int d = 1; d < 512; d <<= 1) {
        int x = (t >= d) ? s[t-d] : 0;
        __syncthreads();
        s[t] += x;
        __syncthreads();
    }
    if (t < SCAN_NB) g_bsum[t] = s[t] - v;       // exclusive
    if (t == 511)    g_off[NV] = s[511];         // total (= 6*NF)
}

__global__ void k_scanC() {
    __shared__ int s[SCAN_CHUNK];
    int t = threadIdx.x;
    int i = blockIdx.x * SCAN_CHUNK + t;
    int v = (i < NV) ? g_deg[i] : 0;
    s[t] = v;
    __syncthreads();
    for (int d = 1; d < SCAN_CHUNK; d <<= 1) {
        int x = (t >= d) ? s[t-d] : 0;
        __syncthreads();
        s[t] += x;
        __syncthreads();
    }
    int ex = s[t] - v + g_bsum[blockIdx.x];
    if (i < NV) { g_off[i] = ex; g_cur[i] = ex; }
}

// ---------------------------------------------------------------------------
// 5) CSR fill: per face, append the 2 neighbors of each corner
// ---------------------------------------------------------------------------
__global__ void k_fill(const void* __restrict__ faces) {
    int f = blockIdx.x * blockDim.x + threadIdx.x;
    if (f >= NF) return;
    int i, j, k;
    load_face(faces, f, i, j, k);
    int p;
    p = atomicAdd(&g_cur[i], 2); g_adj[p] = j; g_adj[p+1] = k;
    p = atomicAdd(&g_cur[j], 2); g_adj[p] = i; g_adj[p+1] = k;
    p = atomicAdd(&g_cur[k], 2); g_adj[p] = i; g_adj[p+1] = j;
}

// ---------------------------------------------------------------------------
// 6) gather + curvature: one warp per vertex, lane e<24 owns element b*3+c.
//    Each neighbor visit = one coalesced 96B read out of L2-resident g_vt.
// ---------------------------------------------------------------------------
__global__ void k_gather() {
    int gw   = (blockIdx.x * blockDim.x + threadIdx.x) >> 5;
    int lane = threadIdx.x & 31;
    if (gw >= NV) return;

    int start = g_off[gw];
    int end   = g_off[gw + 1];
    int deg   = end - start;

    bool act = lane < 24;
    float own = 0.f, acc = 0.f;
    if (act) own = __ldg(&g_vt[(size_t)gw*24 + lane]);

    for (int base = start; base < end; base += 32) {
        int cnt = end - base; if (cnt > 32) cnt = 32;
        int sidx = 0;
        if (lane < cnt) sidx = g_adj[base + lane];
        for (int t = 0; t < cnt; t++) {
            int s = __shfl_sync(0xffffffffu, sidx, t);
            if (act) acc += __ldg(&g_vt[(size_t)s*24 + lane]);
        }
    }

    float inv = 1.f / fmaxf((float)deg, 1.f);
    float lap = acc * inv - own;
    float sq  = lap * lap;
    float s1 = __shfl_down_sync(0xffffffffu, sq, 1);
    float s2 = __shfl_down_sync(0xffffffffu, sq, 2);
    float sum = sq + s1 + s2;
    if (act && (lane % 3) == 0)
        g_ct[(size_t)gw*8 + lane/3] = sqrtf(sum);
}

// ---------------------------------------------------------------------------
// 7) output transpose: g_ct [N][8] -> out [8][N]
// ---------------------------------------------------------------------------
__global__ void k_outT(float* __restrict__ out) {
    __shared__ float s[32*9];             // pad 8->9 to kill bank conflicts
    int n0 = blockIdx.x * 32;
    int t  = threadIdx.x;                 // 256 threads
    {
        int v = t >> 3, e = t & 7;
        s[v*9 + e] = g_ct[(size_t)n0*8 + t];   // coalesced 1KB read
    }
    __syncthreads();
    int b = t >> 5, v = t & 31;
    out[(size_t)b*NV + n0 + v] = s[v*9 + b];   // coalesced 128B per batch row
}

// ---------------------------------------------------------------------------
extern "C" void kernel_launch(void* const* d_in, const int* in_sizes, int n_in,
                              void* d_out, int out_size) {
    const float* vert  = (const float*)d_in[0];   // (8, 500000, 3) f32
    const void*  faces = d_in[1];                 // (1000000, 3) i64 OR i32
    float* out = (float*)d_out;                   // (8, 500000) f32

    // 0) detect faces dtype
    k_probe<<<1, 256>>>((const int*)faces);
    // 1) transpose vertices into [N][24]
    k_transpose<<<(NV + 63) / 64, 192>>>(vert);
    // 2) zero degree
    k_zero_deg<<<(NV + 255) / 256, 256>>>();
    // 3) degree histogram
    k_hist<<<(NF + 255) / 256, 256>>>(faces);
    // 4) exclusive scan -> CSR offsets (+ cursors)
    k_scanA<<<SCAN_NB, SCAN_CHUNK>>>();
    k_scanB<<<1, 512>>>();
    k_scanC<<<SCAN_NB, SCAN_CHUNK>>>();
    // 5) CSR fill
    k_fill<<<(NF + 255) / 256, 256>>>(faces);
    // 6) gather + curvature (warp per vertex)
    k_gather<<<(NV * 32) / 256, 256>>>();
    // 7) output transpose
    k_outT<<<NV / 32, 256>>>(out);
}

// round 3
// speedup vs baseline: 1.1541x; 1.1541x over previous
#include <cuda_runtime.h>
#include <stdint.h>
#include <math.h>

// Problem constants (fixed by the dataset)
#define BB 8
#define NV 500000
#define NF 1000000
#define NE (6*NF)
#define VSTRIDE 32            // padded row: 24 used floats + 8 pad = 128B line

#define SCAN_CHUNK 1024
#define SCAN_NB ((NV + SCAN_CHUNK - 1)/SCAN_CHUNK)   // 489

// ---- device-global scratch (no cudaMalloc allowed) ----
__device__ __align__(128) float g_vt[(size_t)NV*VSTRIDE];  // [N][32] padded rows (64 MB)
__device__ int   g_deg[NV];              // degree histogram
__device__ int   g_off[NV+1];            // CSR offsets (exclusive scan of deg)
__device__ int   g_cur[NV];              // fill cursors
__device__ __align__(16) int g_adj[NE];  // CSR adjacency (src vertex ids)
__device__ int   g_fi[3*NF];             // faces converted to clamped int32
__device__ int   g_bsum[1024];           // scan block sums
__device__ float g_ct[(size_t)NV*BB];    // curvature, vertex-major [N][8]
__device__ int   g_is64;                 // faces dtype flag (1 = int64, 0 = int32)

// ---------------------------------------------------------------------------
// 0) dtype probe: if faces is int64 with values < 500000, every odd 32-bit
//    word is 0. For int32 data that is impossible over 4096 random samples.
// ---------------------------------------------------------------------------
__global__ void k_probe(const int* __restrict__ f) {
    __shared__ int any;
    if (threadIdx.x == 0) any = 0;
    __syncthreads();
    int bad = 0;
    for (int i = threadIdx.x; i < 4096; i += blockDim.x)
        if (f[2*i + 1] != 0) bad = 1;
    if (bad) atomicOr(&any, 1);
    __syncthreads();
    if (threadIdx.x == 0) g_is64 = (any == 0);
}

__device__ __forceinline__ void load_face_raw(const void* faces, int f,
                                              int& i, int& j, int& k) {
    if (g_is64) {
        const long long* p = (const long long*)faces + (size_t)f * 3;
        i = (int)p[0]; j = (int)p[1]; k = (int)p[2];
    } else {
        const int* p = (const int*)faces + (size_t)f * 3;
        i = p[0]; j = p[1]; k = p[2];
    }
    i = min(max(i, 0), NV - 1);
    j = min(max(j, 0), NV - 1);
    k = min(max(k, 0), NV - 1);
}

// ---------------------------------------------------------------------------
// 1) vert (B,N,3) -> vt (N, 32-padded) ; element b*3+c of each row.
// ---------------------------------------------------------------------------
__global__ void k_transpose(const float* __restrict__ vert) {
    __shared__ float s[64*24];
    int n0 = blockIdx.x * 64;
    int t  = threadIdx.x;                 // 192 threads
    int nrem = NV - n0; if (nrem > 64) nrem = 64;
    int cnt = nrem * 3;
    #pragma unroll
    for (int b = 0; b < 8; b++) {
        if (t < cnt) {
            int v = t / 3, c = t - v*3;
            s[v*24 + b*3 + c] = vert[(size_t)b*NV*3 + (size_t)n0*3 + t];
        }
    }
    __syncthreads();
    int tot = nrem * 24;
    for (int i = t; i < tot; i += 192) {
        int v = i / 24, e = i - v*24;
        g_vt[(size_t)(n0 + v)*VSTRIDE + e] = s[i];
    }
}

// ---------------------------------------------------------------------------
// 2) zero degree histogram (graph replays -> must re-init every launch)
// ---------------------------------------------------------------------------
__global__ void k_zero_deg() {
    int i = blockIdx.x * blockDim.x + threadIdx.x;
    if (i < NV) g_deg[i] = 0;
}

// ---------------------------------------------------------------------------
// 3) degree histogram + int32 face conversion (single faces pass)
// ---------------------------------------------------------------------------
__global__ void k_hist(const void* __restrict__ faces) {
    int f = blockIdx.x * blockDim.x + threadIdx.x;
    if (f >= NF) return;
    int i, j, k;
    load_face_raw(faces, f, i, j, k);
    size_t o = (size_t)f * 3;
    g_fi[o] = i; g_fi[o+1] = j; g_fi[o+2] = k;
    atomicAdd(&g_deg[i], 2);
    atomicAdd(&g_deg[j], 2);
    atomicAdd(&g_deg[k], 2);
}

// ---------------------------------------------------------------------------
// 4) two-level exclusive scan: A=block sums, B=scan of sums, C=final offsets
// ---------------------------------------------------------------------------
__global__ void k_scanA() {
    __shared__ int s[SCAN_CHUNK];
    int i = blockIdx.x * SCAN_CHUNK + threadIdx.x;
    s[threadIdx.x] = (i < NV) ? g_deg[i] : 0;
    __syncthreads();
    for (int d = SCAN_CHUNK/2; d > 0; d >>= 1) {
        if (threadIdx.x < d) s[threadIdx.x] += s[threadIdx.x + d];
        __syncthreads();
    }
    if (threadIdx.x == 0) g_bsum[blockIdx.x] = s[0];
}

__global__ void k_scanB() {
    __shared__ int s[512];
    int t = threadIdx.x;                  // 512 threads, SCAN_NB=489 entries
    int v = (t < SCAN_NB) ? g_bsum[t] : 0;
    s[t] = v;
    __syncthreads();
    for (int d = 1; d < 512; d <<= 1) {
        int x = (t >= d) ? s[t-d] : 0;
        __syncthreads();
        s[t] += x;
        __syncthreads();
    }
    if (t < SCAN_NB) g_bsum[t] = s[t] - v;       // exclusive
    if (t == 511)    g_off[NV] = s[511];         // total (= 6*NF)
}

__global__ void k_scanC() {
    __shared__ int s[SCAN_CHUNK];
    int t = threadIdx.x;
    int i = blockIdx.x * SCAN_CHUNK + t;
    int v = (i < NV) ? g_deg[i] : 0;
    s[t] = v;
    __syncthreads();
    for (int d = 1; d < SCAN_CHUNK; d <<= 1) {
        int x = (t >= d) ? s[t-d] : 0;
        __syncthreads();
        s[t] += x;
        __syncthreads();
    }
    int ex = s[t] - v + g_bsum[blockIdx.x];
    if (i < NV) { g_off[i] = ex; g_cur[i] = ex; }
}

// ---------------------------------------------------------------------------
// 5) CSR fill: per face, append the 2 neighbors of each corner (int2 stores)
// ---------------------------------------------------------------------------
__global__ void k_fill() {
    int f = blockIdx.x * blockDim.x + threadIdx.x;
    if (f >= NF) return;
    size_t o = (size_t)f * 3;
    int i = g_fi[o], j = g_fi[o+1], k = g_fi[o+2];
    int p;
    p = atomicAdd(&g_cur[i], 2); *(int2*)&g_adj[p] = make_int2(j, k);
    p = atomicAdd(&g_cur[j], 2); *(int2*)&g_adj[p] = make_int2(i, k);
    p = atomicAdd(&g_cur[k], 2); *(int2*)&g_adj[p] = make_int2(i, j);
}

// ---------------------------------------------------------------------------
// 6) gather + curvature: one warp per vertex, lane e<24 owns element b*3+c.
//    Adjacency read as uniform (warp-broadcast) loads; x4 unroll for MLP.
//    Each neighbor visit = one 128B-line (3 sector) read from L2-resident vt.
// ---------------------------------------------------------------------------
__global__ void k_gather() {
    int gw   = (blockIdx.x * blockDim.x + threadIdx.x) >> 5;
    int lane = threadIdx.x & 31;
    if (gw >= NV) return;

    int start = g_off[gw];
    int end   = g_off[gw + 1];
    int deg   = end - start;

    bool act = lane < 24;
    float own = 0.f, acc = 0.f;
    if (act) own = __ldg(&g_vt[(size_t)gw*VSTRIDE + lane]);

    int e = start;
    for (; e + 4 <= end; e += 4) {
        int s0 = __ldg(&g_adj[e]);
        int s1 = __ldg(&g_adj[e+1]);
        int s2 = __ldg(&g_adj[e+2]);
        int s3 = __ldg(&g_adj[e+3]);
        if (act) {
            float a = __ldg(&g_vt[(size_t)s0*VSTRIDE + lane]);
            float b = __ldg(&g_vt[(size_t)s1*VSTRIDE + lane]);
            float c = __ldg(&g_vt[(size_t)s2*VSTRIDE + lane]);
            float d = __ldg(&g_vt[(size_t)s3*VSTRIDE + lane]);
            acc += (a + b) + (c + d);
        }
    }
    for (; e + 2 <= end; e += 2) {      // degree is always even
        int s0 = __ldg(&g_adj[e]);
        int s1 = __ldg(&g_adj[e+1]);
        if (act) {
            float a = __ldg(&g_vt[(size_t)s0*VSTRIDE + lane]);
            float b = __ldg(&g_vt[(size_t)s1*VSTRIDE + lane]);
            acc += a + b;
        }
    }

    float inv = 1.f / fmaxf((float)deg, 1.f);
    float lap = acc * inv - own;
    float sq  = lap * lap;
    float s1 = __shfl_down_sync(0xffffffffu, sq, 1);
    float s2 = __shfl_down_sync(0xffffffffu, sq, 2);
    float sum = sq + s1 + s2;
    if (act && (lane % 3) == 0)
        g_ct[(size_t)gw*8 + lane/3] = sqrtf(sum);
}

// ---------------------------------------------------------------------------
// 7) output transpose: g_ct [N][8] -> out [8][N]
// ---------------------------------------------------------------------------
__global__ void k_outT(float* __restrict__ out) {
    __shared__ float s[32*9];             // pad 8->9 to kill bank conflicts
    int n0 = blockIdx.x * 32;
    int t  = threadIdx.x;                 // 256 threads
    {
        int v = t >> 3, e = t & 7;
        s[v*9 + e] = g_ct[(size_t)n0*8 + t];   // coalesced 1KB read
    }
    __syncthreads();
    int b = t >> 5, v = t & 31;
    out[(size_t)b*NV + n0 + v] = s[v*9 + b];   // coalesced 128B per batch row
}

// ---------------------------------------------------------------------------
extern "C" void kernel_launch(void* const* d_in, const int* in_sizes, int n_in,
                              void* d_out, int out_size) {
    const float* vert  = (const float*)d_in[0];   // (8, 500000, 3) f32
    const void*  faces = d_in[1];                 // (1000000, 3) i64 OR i32
    float* out = (float*)d_out;                   // (8, 500000) f32

    // 0) detect faces dtype
    k_probe<<<1, 256>>>((const int*)faces);
    // 1) transpose vertices into padded [N][32]
    k_transpose<<<(NV + 63) / 64, 192>>>(vert);
    // 2) zero degree
    k_zero_deg<<<(NV + 255) / 256, 256>>>();
    // 3) degree histogram + int32 conversion
    k_hist<<<(NF + 255) / 256, 256>>>(faces);
    // 4) exclusive scan -> CSR offsets (+ cursors)
    k_scanA<<<SCAN_NB, SCAN_CHUNK>>>();
    k_scanB<<<1, 512>>>();
    k_scanC<<<SCAN_NB, SCAN_CHUNK>>>();
    // 5) CSR fill (int32 faces, int2 stores)
    k_fill<<<(NF + 255) / 256, 256>>>();
    // 6) gather + curvature (warp per vertex)
    k_gather<<<(NV * 32) / 256, 256>>>();
    // 7) output transpose
    k_outT<<<NV / 32, 256>>>(out);
}